// round 7
// baseline (speedup 1.0000x reference)
#include <cuda_runtime.h>
#include <cstdint>

#define MG 4096
#define DD 128
#define K1_BLOCKS 912

// device scratch — no allocation
__device__ float g_pool[MG * DD];

__device__ __forceinline__ void f4add(float4& a, const float4& v) {
    a.x += v.x; a.y += v.y; a.z += v.z; a.w += v.w;
}

// K0: zero pool scratch (K1 accumulates with atomics)
__global__ void k0_zero_pool() {
    int i = blockIdx.x * blockDim.x + threadIdx.x;
    ((float4*)g_pool)[i] = make_float4(0.f, 0.f, 0.f, 0.f);
}

__device__ __forceinline__ void flush_acc(int cur, int c, const float4& a) {
    if (cur >= 0) {
        float* p = &g_pool[(size_t)cur * DD + c * 4];
        atomicAdd(p + 0, a.x);
        atomicAdd(p + 1, a.y);
        atomicAdd(p + 2, a.z);
        atomicAdd(p + 3, a.w);
    }
}

// K1: segment sum, row-balanced TMA pipeline.
// 912 persistent blocks each own an exactly-equal contiguous row range.
// Rows stream in 32-row (16 KB) double-buffered TMA stages; 256 threads =
// 8 row-lanes x 32 float4 chunks consume from smem, accumulating per-lane
// and flushing to g_pool via atomicAdd on segment change (sorted seg).
__global__ void __launch_bounds__(256) k1_seg_sum_tma(const float* __restrict__ h,
                                                      const int* __restrict__ seg,
                                                      int N) {
    __shared__ float4 buf[2][32 * 32];            // 2 x 16 KB stages
    __shared__ __align__(8) unsigned long long mbar_store[2];

    const int tid = threadIdx.x;
    const int c   = tid & 31;
    const int rl  = tid >> 5;

    const uint32_t mb[2] = {
        (uint32_t)__cvta_generic_to_shared(&mbar_store[0]),
        (uint32_t)__cvta_generic_to_shared(&mbar_store[1]) };
    const uint32_t bufa[2] = {
        (uint32_t)__cvta_generic_to_shared(&buf[0][0]),
        (uint32_t)__cvta_generic_to_shared(&buf[1][0]) };

    if (tid == 0) {
        asm volatile("mbarrier.init.shared.b64 [%0], %1;" :: "r"(mb[0]), "r"(1u) : "memory");
        asm volatile("mbarrier.init.shared.b64 [%0], %1;" :: "r"(mb[1]), "r"(1u) : "memory");
    }
    __syncthreads();

    // exact even row partition
    const int start = (int)(((long long)blockIdx.x * N) / K1_BLOCKS);
    const int end   = (int)(((long long)(blockIdx.x + 1) * N) / K1_BLOCKS);
    const int nrows = end - start;
    const int nst   = (nrows + 31) >> 5;

    int ph0 = 0, ph1 = 0;

    #define ISSUE_STAGE(s)                                                              \
        do {                                                                             \
            int _b = (s) & 1;                                                            \
            int _rows = nrows - ((s) << 5); if (_rows > 32) _rows = 32;                  \
            uint32_t _bytes = (uint32_t)_rows << 9;                                      \
            const float* _src = h + ((size_t)(start + ((s) << 5)) << 7);                 \
            asm volatile("mbarrier.arrive.expect_tx.shared.b64 _, [%0], %1;"             \
                         :: "r"(mb[_b]), "r"(_bytes) : "memory");                        \
            asm volatile(                                                                \
                "cp.async.bulk.shared::cluster.global.mbarrier::complete_tx::bytes "     \
                "[%0], [%1], %2, [%3];"                                                  \
                :: "r"(bufa[_b]), "l"(_src), "r"(_bytes), "r"(mb[_b]) : "memory");       \
        } while (0)

    if (tid == 0 && nst > 0) {
        ISSUE_STAGE(0);
        if (nst > 1) ISSUE_STAGE(1);
    }

    float4 acc = make_float4(0.f, 0.f, 0.f, 0.f);
    int cur = -1;

    for (int si = 0; si < nst; ++si) {
        const int b = si & 1;
        const int ph = b ? ph1 : ph0;
        uint32_t done;
        do {
            asm volatile(
                "{\n\t.reg .pred p;\n\t"
                "mbarrier.try_wait.parity.acquire.cta.shared::cta.b64 p, [%1], %2;\n\t"
                "selp.b32 %0, 1, 0, p;\n\t}"
                : "=r"(done) : "r"(mb[b]), "r"((uint32_t)ph) : "memory");
        } while (!done);
        if (b) ph1 ^= 1; else ph0 ^= 1;

        const int srow0 = start + (si << 5);
        int rows_this = nrows - (si << 5); if (rows_this > 32) rows_this = 32;

        // prefetch this stage's seg ids for my 4 rows (L1 broadcast hits)
        int sg[4];
        #pragma unroll
        for (int k = 0; k < 4; ++k) {
            int r = rl + 8 * k;
            sg[k] = (r < rows_this) ? __ldg(seg + srow0 + r) : -1;
        }

        const float4* B = buf[b];
        #pragma unroll
        for (int k = 0; k < 4; ++k) {
            int r = rl + 8 * k;
            if (r < rows_this) {
                if (sg[k] != cur) {
                    flush_acc(cur, c, acc);
                    cur = sg[k];
                    acc = make_float4(0.f, 0.f, 0.f, 0.f);
                }
                f4add(acc, B[r * 32 + c]);
            }
        }
        __syncthreads();   // all threads done reading buf[b]
        if (tid == 0 && si + 2 < nst) ISSUE_STAGE(si + 2);
    }
    #undef ISSUE_STAGE

    flush_acc(cur, c, acc);
}

// K2: vn_out[m] = vn_h[m] + relu((vn_h[m] + pool[m]) @ W^T + b)
__global__ void k2_vn_update(const float* __restrict__ vn_h,
                             const float* __restrict__ W,
                             const float* __restrict__ b,
                             float* __restrict__ vn_out) {
    __shared__ float xs[8][DD];
    const int m0 = blockIdx.x * 8;
    const int j  = threadIdx.x;

    #pragma unroll
    for (int r = 0; r < 8; ++r) {
        int idx = (m0 + r) * DD + j;
        xs[r][j] = vn_h[idx] + g_pool[idx];
    }
    __syncthreads();

    float acc[8] = {0.f, 0.f, 0.f, 0.f, 0.f, 0.f, 0.f, 0.f};
    const float4* Wrow = reinterpret_cast<const float4*>(W + (size_t)j * DD);
    #pragma unroll 8
    for (int k4 = 0; k4 < DD / 4; ++k4) {
        float4 w = Wrow[k4];
        int k = k4 * 4;
        #pragma unroll
        for (int r = 0; r < 8; ++r) {
            acc[r] += xs[r][k + 0] * w.x;
            acc[r] += xs[r][k + 1] * w.y;
            acc[r] += xs[r][k + 2] * w.z;
            acc[r] += xs[r][k + 3] * w.w;
        }
    }

    float bj = b[j];
    #pragma unroll
    for (int r = 0; r < 8; ++r) {
        float t = acc[r] + bj;
        t = t > 0.f ? t : 0.f;
        int idx = (m0 + r) * DD + j;
        vn_out[idx] = vn_h[idx] + t;
    }
}

// K3: h_new[i] = h[i] + vn_new[seg[i]]
// 4 float4 chunks per thread, loads front-batched; streaming hints.
__global__ void k3_broadcast_add(const float* __restrict__ h,
                                 const int* __restrict__ seg,
                                 const float* __restrict__ vn_new,
                                 float* __restrict__ out, int N) {
    const long long total = (long long)N * (DD / 4);
    const long long base = (long long)blockIdx.x * 1024 + threadIdx.x;
    const float4* h4  = reinterpret_cast<const float4*>(h);
    const float4* vn4 = reinterpret_cast<const float4*>(vn_new);
    float4* out4      = reinterpret_cast<float4*>(out);

    if (base + 3 * 256 < total) {
        float4 a[4];
        int s[4];
        #pragma unroll
        for (int i = 0; i < 4; ++i) {
            long long idx = base + (long long)i * 256;
            a[i] = __ldcs(h4 + idx);
            s[i] = __ldg(seg + (int)(idx >> 5));
        }
        #pragma unroll
        for (int i = 0; i < 4; ++i) {
            long long idx = base + (long long)i * 256;
            float4 v = __ldg(vn4 + (long long)s[i] * 32 + (idx & 31));
            a[i].x += v.x; a[i].y += v.y; a[i].z += v.z; a[i].w += v.w;
            __stcs(out4 + idx, a[i]);
        }
    } else {
        #pragma unroll
        for (int i = 0; i < 4; ++i) {
            long long idx = base + (long long)i * 256;
            if (idx >= total) break;
            int s = __ldg(seg + (int)(idx >> 5));
            float4 a = __ldcs(h4 + idx);
            float4 v = __ldg(vn4 + (long long)s * 32 + (idx & 31));
            a.x += v.x; a.y += v.y; a.z += v.z; a.w += v.w;
            __stcs(out4 + idx, a);
        }
    }
}

extern "C" void kernel_launch(void* const* d_in, const int* in_sizes, int n_in,
                              void* d_out, int out_size) {
    const float* h    = (const float*)d_in[0];      // [N, 128]
    const float* vn_h = (const float*)d_in[1];      // [4096, 128]
    const int*   seg  = (const int*)d_in[2];        // [N] sorted int32
    const float* W    = (const float*)d_in[3];      // [128, 128]
    const float* b    = (const float*)d_in[4];      // [128]

    const int N = in_sizes[0] / DD;                   // 1,000,000
    float* out_h  = (float*)d_out;                    // h_new [N,128]
    float* out_vn = (float*)d_out + (size_t)N * DD;   // vn_h_new [4096,128]

    // K0: zero pool (float4 elements: MG*DD/4 = 131072)
    k0_zero_pool<<<(MG * DD / 4) / 256, 256>>>();

    // K1: row-balanced TMA segment sum (912 persistent blocks, 6/SM)
    k1_seg_sum_tma<<<K1_BLOCKS, 256>>>(h, seg, N);

    // K2: virtual-node update
    k2_vn_update<<<MG / 8, DD>>>(vn_h, W, b, out_vn);

    // K3: broadcast-add back to nodes
    long long total4 = (long long)N * (DD / 4);
    int blocks = (int)((total4 + 1023) / 1024);
    k3_broadcast_add<<<blocks, 256>>>(h, seg, out_vn, out_h, N);
}

// round 8
// speedup vs baseline: 1.0310x; 1.0310x over previous
#include <cuda_runtime.h>
#include <cstdint>

#define MG 4096
#define DD 128
#define K1_BLOCKS 912

// device scratch — no allocation
__device__ float g_pool[MG * DD];
__device__ int   g_start[MG + 1];
__device__ unsigned int g_counter;

__device__ __forceinline__ void f4add(float4& a, const float4& v) {
    a.x += v.x; a.y += v.y; a.z += v.z; a.w += v.w;
}

// K0: segment start table from sorted seg + reset work counter.
__global__ void k0_starts(const int* __restrict__ seg, int N) {
    int i = blockIdx.x * blockDim.x + threadIdx.x;
    if (i == 0) g_counter = 0;
    if (i >= N) return;
    int s  = seg[i];
    int sp = (i == 0) ? -1 : seg[i - 1];
    for (int t = sp + 1; t <= s; ++t) g_start[t] = i;
    if (i == N - 1) {
        for (int t = s + 1; t <= MG; ++t) g_start[t] = N;
    }
}

// K1: segment sum via TMA bulk pipeline + segment work-stealing.
// 912 persistent blocks; each grabs segments from a global counter (perfect
// load balance, single wave). Per segment: rows stream in 32-row (16 KB)
// double-buffered cp.async.bulk stages; 256 threads (8 row-lanes x 32 float4
// chunks) reduce from smem; shared tree reduction writes g_pool. No atomics
// on data.
__global__ void __launch_bounds__(256) k1_seg_sum_tma(const float* __restrict__ h) {
    __shared__ float4 buf[2][32 * 32];            // 2 x 16 KB stages
    __shared__ float4 sred[8][32];                // 4 KB reduction scratch
    __shared__ int sm;                            // stolen segment id
    __shared__ __align__(8) unsigned long long mbar_store[2];

    const int tid = threadIdx.x;
    const int c   = tid & 31;
    const int rl  = tid >> 5;

    const uint32_t mb0  = (uint32_t)__cvta_generic_to_shared(&mbar_store[0]);
    const uint32_t mb1  = (uint32_t)__cvta_generic_to_shared(&mbar_store[1]);
    const uint32_t bufa0 = (uint32_t)__cvta_generic_to_shared(&buf[0][0]);
    const uint32_t bufa1 = (uint32_t)__cvta_generic_to_shared(&buf[1][0]);

    if (tid == 0) {
        asm volatile("mbarrier.init.shared.b64 [%0], %1;" :: "r"(mb0), "r"(1u) : "memory");
        asm volatile("mbarrier.init.shared.b64 [%0], %1;" :: "r"(mb1), "r"(1u) : "memory");
    }
    __syncthreads();

    int ph0 = 0, ph1 = 0;   // per-slot phase parity

    for (;;) {
        if (tid == 0) sm = (int)atomicAdd(&g_counter, 1u);
        __syncthreads();
        const int m = sm;
        if (m >= MG) break;

        const int start = g_start[m];
        const int end   = g_start[m + 1];
        const int nrows = end - start;

        float4 a0 = make_float4(0.f, 0.f, 0.f, 0.f);
        float4 a1 = make_float4(0.f, 0.f, 0.f, 0.f);

        if (nrows > 0) {
            const int nst = (nrows + 31) >> 5;

            #define ISSUE_STAGE(s)                                                         \
                do {                                                                        \
                    int _b = (s) & 1;                                                       \
                    int _rows = nrows - ((s) << 5); if (_rows > 32) _rows = 32;             \
                    uint32_t _bytes = (uint32_t)_rows << 9;                                 \
                    uint32_t _mb  = _b ? mb1 : mb0;                                         \
                    uint32_t _dst = _b ? bufa1 : bufa0;                                     \
                    const float* _src = h + ((size_t)(start + ((s) << 5)) << 7);            \
                    asm volatile("mbarrier.arrive.expect_tx.shared.b64 _, [%0], %1;"        \
                                 :: "r"(_mb), "r"(_bytes) : "memory");                      \
                    asm volatile(                                                           \
                        "cp.async.bulk.shared::cluster.global.mbarrier::complete_tx::bytes "\
                        "[%0], [%1], %2, [%3];"                                             \
                        :: "r"(_dst), "l"(_src), "r"(_bytes), "r"(_mb) : "memory");         \
                } while (0)

            if (tid == 0) {
                ISSUE_STAGE(0);
                if (nst > 1) ISSUE_STAGE(1);
            }

            for (int si = 0; si < nst; ++si) {
                const int b = si & 1;
                const uint32_t mb = b ? mb1 : mb0;
                const int ph = b ? ph1 : ph0;
                uint32_t done;
                do {
                    asm volatile(
                        "{\n\t.reg .pred p;\n\t"
                        "mbarrier.try_wait.parity.acquire.cta.shared::cta.b64 p, [%1], %2;\n\t"
                        "selp.b32 %0, 1, 0, p;\n\t}"
                        : "=r"(done) : "r"(mb), "r"((uint32_t)ph) : "memory");
                } while (!done);
                if (b) ph1 ^= 1; else ph0 ^= 1;

                int rows_this = nrows - (si << 5); if (rows_this > 32) rows_this = 32;
                const float4* B = buf[b];
                if (rows_this == 32) {
                    float4 v0 = B[(rl)      * 32 + c];
                    float4 v1 = B[(rl + 8)  * 32 + c];
                    float4 v2 = B[(rl + 16) * 32 + c];
                    float4 v3 = B[(rl + 24) * 32 + c];
                    f4add(a0, v0); f4add(a1, v1); f4add(a0, v2); f4add(a1, v3);
                } else {
                    #pragma unroll
                    for (int k = 0; k < 4; ++k) {
                        int r = rl + 8 * k;
                        if (r < rows_this) f4add(a0, B[r * 32 + c]);
                    }
                }
                __syncthreads();   // everyone done reading buf[b]
                if (tid == 0 && si + 2 < nst) ISSUE_STAGE(si + 2);
            }
            #undef ISSUE_STAGE
        }

        f4add(a0, a1);
        sred[rl][c] = a0;
        __syncthreads();
        if (rl < 4) { f4add(a0, sred[rl + 4][c]); sred[rl][c] = a0; }
        __syncthreads();
        if (rl < 2) { f4add(a0, sred[rl + 2][c]); sred[rl][c] = a0; }
        __syncthreads();
        if (rl == 0) {
            f4add(a0, sred[1][c]);
            reinterpret_cast<float4*>(g_pool)[(size_t)m * 32 + c] = a0;
        }
        __syncthreads();
    }
}

// K2: vn_out[m] = vn_h[m] + relu((vn_h[m] + pool[m]) @ W^T + b)
__global__ void k2_vn_update(const float* __restrict__ vn_h,
                             const float* __restrict__ W,
                             const float* __restrict__ b,
                             float* __restrict__ vn_out) {
    __shared__ float xs[8][DD];
    const int m0 = blockIdx.x * 8;
    const int j  = threadIdx.x;

    #pragma unroll
    for (int r = 0; r < 8; ++r) {
        int idx = (m0 + r) * DD + j;
        xs[r][j] = vn_h[idx] + g_pool[idx];
    }
    __syncthreads();

    float acc[8] = {0.f, 0.f, 0.f, 0.f, 0.f, 0.f, 0.f, 0.f};
    const float4* Wrow = reinterpret_cast<const float4*>(W + (size_t)j * DD);
    #pragma unroll 8
    for (int k4 = 0; k4 < DD / 4; ++k4) {
        float4 w = Wrow[k4];
        int k = k4 * 4;
        #pragma unroll
        for (int r = 0; r < 8; ++r) {
            acc[r] += xs[r][k + 0] * w.x;
            acc[r] += xs[r][k + 1] * w.y;
            acc[r] += xs[r][k + 2] * w.z;
            acc[r] += xs[r][k + 3] * w.w;
        }
    }

    float bj = b[j];
    #pragma unroll
    for (int r = 0; r < 8; ++r) {
        float t = acc[r] + bj;
        t = t > 0.f ? t : 0.f;
        int idx = (m0 + r) * DD + j;
        vn_out[idx] = vn_h[idx] + t;
    }
}

// K3: h_new[i] = h[i] + vn_new[seg[i]]
// 4 float4 chunks per thread, loads front-batched; streaming hints.
__global__ void k3_broadcast_add(const float* __restrict__ h,
                                 const int* __restrict__ seg,
                                 const float* __restrict__ vn_new,
                                 float* __restrict__ out, int N) {
    const long long total = (long long)N * (DD / 4);
    const long long base = (long long)blockIdx.x * 1024 + threadIdx.x;
    const float4* h4  = reinterpret_cast<const float4*>(h);
    const float4* vn4 = reinterpret_cast<const float4*>(vn_new);
    float4* out4      = reinterpret_cast<float4*>(out);

    if (base + 3 * 256 < total) {
        float4 a[4];
        int s[4];
        #pragma unroll
        for (int i = 0; i < 4; ++i) {
            long long idx = base + (long long)i * 256;
            a[i] = __ldcs(h4 + idx);
            s[i] = __ldg(seg + (int)(idx >> 5));
        }
        #pragma unroll
        for (int i = 0; i < 4; ++i) {
            long long idx = base + (long long)i * 256;
            float4 v = __ldg(vn4 + (long long)s[i] * 32 + (idx & 31));
            a[i].x += v.x; a[i].y += v.y; a[i].z += v.z; a[i].w += v.w;
            __stcs(out4 + idx, a[i]);
        }
    } else {
        #pragma unroll
        for (int i = 0; i < 4; ++i) {
            long long idx = base + (long long)i * 256;
            if (idx >= total) break;
            int s = __ldg(seg + (int)(idx >> 5));
            float4 a = __ldcs(h4 + idx);
            float4 v = __ldg(vn4 + (long long)s * 32 + (idx & 31));
            a.x += v.x; a.y += v.y; a.z += v.z; a.w += v.w;
            __stcs(out4 + idx, a);
        }
    }
}

extern "C" void kernel_launch(void* const* d_in, const int* in_sizes, int n_in,
                              void* d_out, int out_size) {
    const float* h    = (const float*)d_in[0];      // [N, 128]
    const float* vn_h = (const float*)d_in[1];      // [4096, 128]
    const int*   seg  = (const int*)d_in[2];        // [N] sorted int32
    const float* W    = (const float*)d_in[3];      // [128, 128]
    const float* b    = (const float*)d_in[4];      // [128]

    const int N = in_sizes[0] / DD;                   // 1,000,000
    float* out_h  = (float*)d_out;                    // h_new [N,128]
    float* out_vn = (float*)d_out + (size_t)N * DD;   // vn_h_new [4096,128]

    // K0: segment start table + counter reset
    k0_starts<<<(N + 255) / 256, 256>>>(seg, N);

    // K1: work-stealing TMA segment sum (912 persistent blocks, 6/SM)
    k1_seg_sum_tma<<<K1_BLOCKS, 256>>>(h);

    // K2: virtual-node update
    k2_vn_update<<<MG / 8, DD>>>(vn_h, W, b, out_vn);

    // K3: broadcast-add back to nodes
    long long total4 = (long long)N * (DD / 4);
    int blocks = (int)((total4 + 1023) / 1024);
    k3_broadcast_add<<<blocks, 256>>>(h, seg, out_vn, out_h, N);
}